// round 16
// baseline (speedup 1.0000x reference)
#include <cuda_runtime.h>
#include <cuda_fp16.h>
#include <cstdint>

// Problem shape (fixed): B=4, S=8192 -> M=32768 tokens, H=1024, I=4096, fp32.
#define M_TOK 32768
#define HDIM  1024
#define IDIM  4096

// ---------------------------------------------------------------------------
// Scratch (device globals; no allocation allowed)
// ---------------------------------------------------------------------------
__device__ __half g_xnorm[(size_t)M_TOK * HDIM];  // 64 MB  (LN out, fp16)
__device__ __half g_resadd[(size_t)M_TOK * HDIM]; // 64 MB  (pre-norm sum, fp16)
__device__ __half g_h[(size_t)M_TOK * IDIM];      // 256 MB (GELU out, fp16)
__device__ __half g_wt1[(size_t)IDIM * HDIM];     // inter_w^T  [I,H] fp16
__device__ __half g_wt2[(size_t)HDIM * IDIM];     // output_w^T [H,I] fp16

// ---------------------------------------------------------------------------
// Helpers
// ---------------------------------------------------------------------------
__device__ __forceinline__ void cp_async16(uint32_t smem_addr, const void* gptr) {
    asm volatile("cp.async.cg.shared.global [%0], [%1], 16;\n"
                 :: "r"(smem_addr), "l"(gptr));
}

__device__ __forceinline__ void ldsm4(uint32_t r[4], uint32_t addr) {
    asm volatile("ldmatrix.sync.aligned.m8n8.x4.shared.b16 {%0,%1,%2,%3}, [%4];"
                 : "=r"(r[0]), "=r"(r[1]), "=r"(r[2]), "=r"(r[3]) : "r"(addr));
}

// fp16 MMA, fp32 accumulate: D[16,8] += A[16,16] * B[16,8]
__device__ __forceinline__ void mma_f16(float c[4], const uint32_t a[4],
                                        uint32_t b0, uint32_t b1) {
    asm volatile(
        "mma.sync.aligned.m16n8k16.row.col.f32.f16.f16.f32 "
        "{%0,%1,%2,%3}, {%4,%5,%6,%7}, {%8,%9}, {%0,%1,%2,%3};\n"
        : "+f"(c[0]), "+f"(c[1]), "+f"(c[2]), "+f"(c[3])
        : "r"(a[0]), "r"(a[1]), "r"(a[2]), "r"(a[3]), "r"(b0), "r"(b1));
}

__device__ __forceinline__ float tanh_approx(float x) {
    float y;
    asm("tanh.approx.f32 %0, %1;" : "=f"(y) : "f"(x));
    return y;
}
__device__ __forceinline__ float gelu_tanh(float v) {
    float c = 0.7978845608028654f * (v + 0.044715f * v * v * v);
    return 0.5f * v * (1.0f + tanh_approx(c));
}

// ---------------------------------------------------------------------------
// Kernel 1: fused bias + residual add + LayerNorm.
// 512 threads = 4 rows per block; 128 threads/row x 8 floats/thread.
// Four independent float4 loads per thread (MLP=4) for latency hiding.
// Outputs: xnorm fp16, resadd fp16.
// ---------------------------------------------------------------------------
__global__ void __launch_bounds__(512) fused_add_ln(
    const float* __restrict__ inp, const float* __restrict__ resid,
    const float* __restrict__ bias, const float* __restrict__ gw,
    const float* __restrict__ gb, __half* __restrict__ xn,
    __half* __restrict__ ra)
{
    const int rid = threadIdx.x >> 7;              // 0..3: row within block
    const int t   = threadIdx.x & 127;             // 0..127 within row
    const int row = blockIdx.x * 4 + rid;
    const size_t base = (size_t)row * HDIM + t * 8;

    const float4 x0 = *(const float4*)(inp + base);
    const float4 x1 = *(const float4*)(inp + base + 4);
    const float4 r0 = *(const float4*)(resid + base);
    const float4 r1 = *(const float4*)(resid + base + 4);
    const float4 b0 = *(const float4*)(bias + t * 8);
    const float4 b1 = *(const float4*)(bias + t * 8 + 4);

    float4 s0, s1;
    s0.x = x0.x + b0.x + r0.x;  s0.y = x0.y + b0.y + r0.y;
    s0.z = x0.z + b0.z + r0.z;  s0.w = x0.w + b0.w + r0.w;
    s1.x = x1.x + b1.x + r1.x;  s1.y = x1.y + b1.y + r1.y;
    s1.z = x1.z + b1.z + r1.z;  s1.w = x1.w + b1.w + r1.w;
    {
        __half2* ro = (__half2*)(ra + base);
        ro[0] = __floats2half2_rn(s0.x, s0.y);
        ro[1] = __floats2half2_rn(s0.z, s0.w);
        ro[2] = __floats2half2_rn(s1.x, s1.y);
        ro[3] = __floats2half2_rn(s1.z, s1.w);
    }

    float sum = s0.x + s0.y + s0.z + s0.w + s1.x + s1.y + s1.z + s1.w;
    float sq  = s0.x*s0.x + s0.y*s0.y + s0.z*s0.z + s0.w*s0.w
              + s1.x*s1.x + s1.y*s1.y + s1.z*s1.z + s1.w*s1.w;

    #pragma unroll
    for (int o = 16; o > 0; o >>= 1) {
        sum += __shfl_xor_sync(0xFFFFFFFFu, sum, o);
        sq  += __shfl_xor_sync(0xFFFFFFFFu, sq, o);
    }
    __shared__ float red[4][8];        // [row][warp]: 4 sums + 4 sqs
    __shared__ float stats[4][2];      // [row]: {mean, rstd-input}
    const int w = t >> 5, lane = t & 31;   // 4 warps per row
    if (lane == 0) { red[rid][w] = sum; red[rid][4 + w] = sq; }
    __syncthreads();
    if (t == 0) {
        float s = red[rid][0] + red[rid][1] + red[rid][2] + red[rid][3];
        float q = red[rid][4] + red[rid][5] + red[rid][6] + red[rid][7];
        stats[rid][0] = s * (1.0f / HDIM);
        stats[rid][1] = q * (1.0f / HDIM);
    }
    __syncthreads();
    const float mean = stats[rid][0];
    const float var  = stats[rid][1] - mean * mean;
    const float rstd = rsqrtf(var + 1e-5f);

    const float4 w0 = *(const float4*)(gw + t * 8);
    const float4 w1 = *(const float4*)(gw + t * 8 + 4);
    const float4 e0 = *(const float4*)(gb + t * 8);
    const float4 e1 = *(const float4*)(gb + t * 8 + 4);
    __half2* xo = (__half2*)(xn + base);
    xo[0] = __floats2half2_rn((s0.x - mean) * rstd * w0.x + e0.x,
                              (s0.y - mean) * rstd * w0.y + e0.y);
    xo[1] = __floats2half2_rn((s0.z - mean) * rstd * w0.z + e0.z,
                              (s0.w - mean) * rstd * w0.w + e0.w);
    xo[2] = __floats2half2_rn((s1.x - mean) * rstd * w1.x + e1.x,
                              (s1.y - mean) * rstd * w1.y + e1.y);
    xo[3] = __floats2half2_rn((s1.z - mean) * rstd * w1.z + e1.z,
                              (s1.w - mean) * rstd * w1.w + e1.w);
}

// ---------------------------------------------------------------------------
// Kernel: both weight transposes in ONE launch (blockIdx.z selects matrix).
// 32x32 tiles, fp32 in -> fp16 out (out[c][r] = in[r][c]).
// z=0: inter_w [H,I] -> wt1 [I,H];  z=1: output_w [I,H] -> wt2 [H,I]
// Grid: (128, 128, 2) covers the larger case; z-specific bounds checked.
// ---------------------------------------------------------------------------
__global__ void __launch_bounds__(256) transpose_both(
    const float* __restrict__ w1in, __half* __restrict__ w1out,
    const float* __restrict__ w2in, __half* __restrict__ w2out)
{
    const int z = blockIdx.z;
    const float* in  = z ? w2in  : w1in;
    __half*      out = z ? w2out : w1out;
    const int R = z ? IDIM : HDIM;    // rows of input
    const int C = z ? HDIM : IDIM;    // cols of input
    const int c0 = blockIdx.x * 32, r0 = blockIdx.y * 32;
    if (c0 >= C || r0 >= R) return;

    __shared__ float t[32][33];
    #pragma unroll
    for (int i = threadIdx.y; i < 32; i += 8)
        t[i][threadIdx.x] = in[(size_t)(r0 + i) * C + c0 + threadIdx.x];
    __syncthreads();
    #pragma unroll
    for (int i = threadIdx.y; i < 32; i += 8)
        out[(size_t)(c0 + i) * R + r0 + threadIdx.x] = __float2half_rn(t[threadIdx.x][i]);
}

// ---------------------------------------------------------------------------
// FP16 GEMM (fp32 accumulate): C[M,N] = A[M,K] @ Bt[N,K]^T
// (+bias, +GELU->half or +fp16 residual->f32)
// CTA tile 128x128x64, 8 warps (4Mx2N), warp tile 32x64, m16n8k16 HMMA.
// 3-stage cp.async pipeline, one __syncthreads per k-iter, 2 CTAs/SM
// (16 warps/SM). Proven best config: 98% of the legacy HMMA.F32 pipe
// rate (0.333 MMA/cyc/SM) — the toolchain's tensor ceiling without
// sm_103a-gated tcgen05.
// ---------------------------------------------------------------------------
#define BM 128
#define BN 128
#define BKH 64                        // halves per K-slab (128 bytes)
#define KSTH 72                       // smem row stride in halves (64 + 8 pad)
#define A_HALVES (BM * KSTH)          // 9216
#define B_HALVES (BN * KSTH)          // 9216
#define STAGE_HALVES (A_HALVES + B_HALVES)   // 18432
#define NSTG 3
#define SMEM_BYTES (NSTG * STAGE_HALVES * 2) // 110592

template <bool GELU>
__global__ void __launch_bounds__(256, 2) gemm_f16(
    const __half* __restrict__ A, const __half* __restrict__ Bt,
    const float* __restrict__ bias, const __half* __restrict__ res,
    void* __restrict__ Cv, int N, int K)
{
    extern __shared__ __half smh[];
    const uint32_t sm0 = (uint32_t)__cvta_generic_to_shared(smh);

    const int tid = threadIdx.x;
    const int warp = tid >> 5, lane = tid & 31;
    const int wm = warp >> 1, wn = warp & 1;     // 4 (M) x 2 (N)
    const int row0 = blockIdx.y * BM;
    const int col0 = blockIdx.x * BN;
    const int g = lane >> 2, tq = lane & 3;

    // ldmatrix per-thread address components (in halves)
    const int a_row = wm * 32 + (lane & 15);
    const int a_k   = (lane >> 4) * 8;
    const int b_row = wn * 64 + ((lane & 7) | ((lane >> 1) & 8));
    const int b_k   = ((lane >> 3) & 1) * 8;

    float acc[2][8][4];
    #pragma unroll
    for (int mi = 0; mi < 2; mi++)
        #pragma unroll
        for (int j = 0; j < 8; j++)
            #pragma unroll
            for (int q = 0; q < 4; q++) acc[mi][j][q] = 0.0f;

    const int nK = K / BKH;

    auto load_stage = [&](int kt, int s) {
        __half* As = smh + s * STAGE_HALVES;
        __half* Bs = As + A_HALVES;
        const __half* Ag = A + (size_t)row0 * K + kt * BKH;
        const __half* Bg = Bt + (size_t)col0 * K + kt * BKH;
        #pragma unroll
        for (int i = 0; i < 4; i++) {          // A: 1024 chunks of 16B (8 halves)
            int c = tid + 256 * i;
            int r = c >> 3, o = (c & 7) * 8;
            cp_async16((uint32_t)__cvta_generic_to_shared(As + r * KSTH + o),
                       Ag + (size_t)r * K + o);
        }
        #pragma unroll
        for (int i = 0; i < 4; i++) {          // B: 1024 chunks of 16B
            int c = tid + 256 * i;
            int r = c >> 3, o = (c & 7) * 8;
            cp_async16((uint32_t)__cvta_generic_to_shared(Bs + r * KSTH + o),
                       Bg + (size_t)r * K + o);
        }
        asm volatile("cp.async.commit_group;\n");
    };

    // prefill 2 stages (tiles 0,1 -> 2 groups)
    load_stage(0, 0);
    load_stage(1, 1);

    for (int kt = 0; kt < nK; kt++) {
        const int s = kt % NSTG;
        // tile kt complete in THIS thread (only tile kt+1's group may pend)
        asm volatile("cp.async.wait_group 1;\n");
        // publish all threads' copies of tile kt; also: everyone is done
        // reading stage (kt-1)%NSTG, which gets overwritten below
        __syncthreads();
        if (kt + 2 < nK) {
            load_stage(kt + 2, (kt + 2) % NSTG);       // commits 1 group
        } else {
            asm volatile("cp.async.commit_group;\n");  // keep group-count invariant
        }

        const uint32_t As_u = sm0 + (s * STAGE_HALVES) * 2;
        const uint32_t Bs_u = As_u + A_HALVES * 2;
        const uint32_t a_addr = As_u + (a_row * KSTH + a_k) * 2;
        const uint32_t b_addr = Bs_u + (b_row * KSTH + b_k) * 2;

        #pragma unroll
        for (int kk = 0; kk < BKH; kk += 16) {
            uint32_t af[2][4], bf[4][4];
            #pragma unroll
            for (int mi = 0; mi < 2; mi++)
                ldsm4(af[mi], a_addr + (mi * 16 * KSTH + kk) * 2);
            #pragma unroll
            for (int p = 0; p < 4; p++)
                ldsm4(bf[p], b_addr + (p * 16 * KSTH + kk) * 2);
            #pragma unroll
            for (int mi = 0; mi < 2; mi++)
                #pragma unroll
                for (int j = 0; j < 8; j++)
                    mma_f16(acc[mi][j], af[mi],
                            bf[j >> 1][(j & 1) * 2], bf[j >> 1][(j & 1) * 2 + 1]);
        }
    }

    // Epilogue: register -> gmem
    #pragma unroll
    for (int mi = 0; mi < 2; mi++) {
        const int r0 = row0 + wm * 32 + mi * 16 + g;
        const int r1 = r0 + 8;
        #pragma unroll
        for (int j = 0; j < 8; j++) {
            const int c = col0 + wn * 64 + j * 8 + tq * 2;
            const float b0 = bias[c], b1 = bias[c + 1];
            float v00 = acc[mi][j][0] + b0;
            float v01 = acc[mi][j][1] + b1;
            float v10 = acc[mi][j][2] + b0;
            float v11 = acc[mi][j][3] + b1;
            if (GELU) {
                __half* Ch = (__half*)Cv;
                v00 = gelu_tanh(v00); v01 = gelu_tanh(v01);
                v10 = gelu_tanh(v10); v11 = gelu_tanh(v11);
                *(__half2*)(Ch + (size_t)r0 * N + c) = __floats2half2_rn(v00, v01);
                *(__half2*)(Ch + (size_t)r1 * N + c) = __floats2half2_rn(v10, v11);
            } else {
                float* Cf = (float*)Cv;
                const float2 ra0 = __half22float2(*(const __half2*)(res + (size_t)r0 * N + c));
                const float2 ra1 = __half22float2(*(const __half2*)(res + (size_t)r1 * N + c));
                v00 += ra0.x; v01 += ra0.y;
                v10 += ra1.x; v11 += ra1.y;
                *(float2*)(Cf + (size_t)r0 * N + c) = make_float2(v00, v01);
                *(float2*)(Cf + (size_t)r1 * N + c) = make_float2(v10, v11);
            }
        }
    }
}

// ---------------------------------------------------------------------------
// Launch
// ---------------------------------------------------------------------------
extern "C" void kernel_launch(void* const* d_in, const int* in_sizes, int n_in,
                              void* d_out, int out_size)
{
    const float* input    = (const float*)d_in[0];
    const float* residual = (const float*)d_in[1];
    const float* bias     = (const float*)d_in[3];
    const float* attn_nw  = (const float*)d_in[4];
    const float* attn_nb  = (const float*)d_in[5];
    const float* inter_w  = (const float*)d_in[6];
    const float* inter_b  = (const float*)d_in[7];
    const float* output_w = (const float*)d_in[8];
    const float* output_b = (const float*)d_in[9];
    float* out = (float*)d_out;

    __half *xn, *ra, *hbuf, *wt1, *wt2;
    cudaGetSymbolAddress((void**)&xn,   g_xnorm);
    cudaGetSymbolAddress((void**)&ra,   g_resadd);
    cudaGetSymbolAddress((void**)&hbuf, g_h);
    cudaGetSymbolAddress((void**)&wt1,  g_wt1);
    cudaGetSymbolAddress((void**)&wt2,  g_wt2);

    cudaFuncSetAttribute(gemm_f16<true>,
                         cudaFuncAttributeMaxDynamicSharedMemorySize, SMEM_BYTES);
    cudaFuncSetAttribute(gemm_f16<false>,
                         cudaFuncAttributeMaxDynamicSharedMemorySize, SMEM_BYTES);

    // both weight transposes in one launch (z=0: inter_w, z=1: output_w)
    transpose_both<<<dim3(IDIM / 32, IDIM / 32, 2), dim3(32, 8)>>>(
        inter_w, wt1, output_w, wt2);

    // 1) fused bias + residual + LN (4 rows per block, 8 floats/thread)
    fused_add_ln<<<M_TOK / 4, 512>>>(input, residual, bias, attn_nw, attn_nb, xn, ra);

    // 2) h = gelu(x @ inter_w + inter_b)  [32768,4096] fp16
    gemm_f16<true><<<dim3(IDIM / BN, M_TOK / BM), 256, SMEM_BYTES>>>(
        xn, wt1, inter_b, nullptr, hbuf, IDIM, HDIM);

    // 3) out = h @ output_w + output_b + residual_add  [32768,1024] fp32
    gemm_f16<false><<<dim3(HDIM / BN, M_TOK / BM), 256, SMEM_BYTES>>>(
        hbuf, wt2, output_b, ra, out, HDIM, IDIM);
}

// round 17
// speedup vs baseline: 1.0072x; 1.0072x over previous
#include <cuda_runtime.h>
#include <cuda_fp16.h>
#include <cstdint>

// Problem shape (fixed): B=4, S=8192 -> M=32768 tokens, H=1024, I=4096, fp32.
#define M_TOK 32768
#define HDIM  1024
#define IDIM  4096

// ---------------------------------------------------------------------------
// Scratch (device globals; no allocation allowed)
// ---------------------------------------------------------------------------
__device__ __half g_xnorm[(size_t)M_TOK * HDIM];  // 64 MB  (LN out, fp16)
__device__ __half g_resadd[(size_t)M_TOK * HDIM]; // 64 MB  (pre-norm sum, fp16)
__device__ __half g_h[(size_t)M_TOK * IDIM];      // 256 MB (GELU out, fp16)
__device__ __half g_wt1[(size_t)IDIM * HDIM];     // inter_w^T  [I,H] fp16
__device__ __half g_wt2[(size_t)HDIM * IDIM];     // output_w^T [H,I] fp16

// ---------------------------------------------------------------------------
// Helpers
// ---------------------------------------------------------------------------
__device__ __forceinline__ void cp_async16(uint32_t smem_addr, const void* gptr) {
    asm volatile("cp.async.cg.shared.global [%0], [%1], 16;\n"
                 :: "r"(smem_addr), "l"(gptr));
}

__device__ __forceinline__ void ldsm4(uint32_t r[4], uint32_t addr) {
    asm volatile("ldmatrix.sync.aligned.m8n8.x4.shared.b16 {%0,%1,%2,%3}, [%4];"
                 : "=r"(r[0]), "=r"(r[1]), "=r"(r[2]), "=r"(r[3]) : "r"(addr));
}

// fp16 MMA, fp32 accumulate: D[16,8] += A[16,16] * B[16,8]
__device__ __forceinline__ void mma_f16(float c[4], const uint32_t a[4],
                                        uint32_t b0, uint32_t b1) {
    asm volatile(
        "mma.sync.aligned.m16n8k16.row.col.f32.f16.f16.f32 "
        "{%0,%1,%2,%3}, {%4,%5,%6,%7}, {%8,%9}, {%0,%1,%2,%3};\n"
        : "+f"(c[0]), "+f"(c[1]), "+f"(c[2]), "+f"(c[3])
        : "r"(a[0]), "r"(a[1]), "r"(a[2]), "r"(a[3]), "r"(b0), "r"(b1));
}

__device__ __forceinline__ float tanh_approx(float x) {
    float y;
    asm("tanh.approx.f32 %0, %1;" : "=f"(y) : "f"(x));
    return y;
}
__device__ __forceinline__ float gelu_tanh(float v) {
    float c = 0.7978845608028654f * (v + 0.044715f * v * v * v);
    return 0.5f * v * (1.0f + tanh_approx(c));
}

// ---------------------------------------------------------------------------
// Prep kernel (single launch): LN blocks + weight-transpose blocks.
//   blocks [0, M_TOK/2):            fused bias+residual+LayerNorm, 2 rows/block
//   blocks [M_TOK/2, +4096):        transpose inter_w  [H,I] -> wt1 [I,H]
//   blocks [M_TOK/2+4096, +4096):   transpose output_w [I,H] -> wt2 [H,I]
// 512 threads. Branch is uniform per block; SMEM is a union.
// ---------------------------------------------------------------------------
#define LN_BLOCKS   (M_TOK / 2)                  // 16384
#define T1_TILES    ((IDIM / 32) * (HDIM / 32))  // 4096
#define PREP_BLOCKS (LN_BLOCKS + 2 * T1_TILES)   // 24576

__global__ void __launch_bounds__(512) prep_kernel(
    const float* __restrict__ inp, const float* __restrict__ resid,
    const float* __restrict__ bias, const float* __restrict__ gw,
    const float* __restrict__ gb, __half* __restrict__ xn,
    __half* __restrict__ ra,
    const float* __restrict__ w1in, __half* __restrict__ w1out,
    const float* __restrict__ w2in, __half* __restrict__ w2out)
{
    __shared__ float shm[32 * 33];   // transpose tile; LN uses first 32 floats

    const int bid = blockIdx.x;
    if (bid < LN_BLOCKS) {
        // ---- LayerNorm part (R14-proven shape: 2 rows, 256 threads/row) ----
        const int half_id = threadIdx.x >> 8;          // 0 or 1: which row
        const int t = threadIdx.x & 255;               // 0..255 within row
        const int row = bid * 2 + half_id;
        const size_t base = (size_t)row * HDIM + t * 4;

        float4 x = *(const float4*)(inp + base);
        float4 r = *(const float4*)(resid + base);
        float4 b = *(const float4*)(bias + t * 4);

        float4 s;
        s.x = x.x + b.x + r.x;
        s.y = x.y + b.y + r.y;
        s.z = x.z + b.z + r.z;
        s.w = x.w + b.w + r.w;
        {
            __half2* ro = (__half2*)(ra + base);
            ro[0] = __floats2half2_rn(s.x, s.y);
            ro[1] = __floats2half2_rn(s.z, s.w);
        }

        float sum = s.x + s.y + s.z + s.w;
        float sq  = s.x * s.x + s.y * s.y + s.z * s.z + s.w * s.w;

        #pragma unroll
        for (int o = 16; o > 0; o >>= 1) {
            sum += __shfl_xor_sync(0xFFFFFFFFu, sum, o);
            sq  += __shfl_xor_sync(0xFFFFFFFFu, sq, o);
        }
        float* red = shm + half_id * 16;   // [2][16]
        const int warp = t >> 5, lane = t & 31;
        if (lane == 0) { red[warp] = sum; red[8 + warp] = sq; }
        __syncthreads();
        if (t == 0) {
            float s0 = 0.f, q0 = 0.f;
            #pragma unroll
            for (int i = 0; i < 8; i++) { s0 += red[i]; q0 += red[8 + i]; }
            red[0] = s0; red[8] = q0;
        }
        __syncthreads();
        const float mean = red[0] * (1.0f / HDIM);
        const float var  = red[8] * (1.0f / HDIM) - mean * mean;
        const float rstd = rsqrtf(var + 1e-5f);

        float4 w = *(const float4*)(gw + t * 4);
        float4 be = *(const float4*)(gb + t * 4);
        float o0 = (s.x - mean) * rstd * w.x + be.x;
        float o1 = (s.y - mean) * rstd * w.y + be.y;
        float o2 = (s.z - mean) * rstd * w.z + be.z;
        float o3 = (s.w - mean) * rstd * w.w + be.w;
        __half2* xo = (__half2*)(xn + base);
        xo[0] = __floats2half2_rn(o0, o1);
        xo[1] = __floats2half2_rn(o2, o3);
    } else {
        // ---- transpose part: exactly-sized tiles, 512 threads = 32x16 ----
        int tile = bid - LN_BLOCKS;
        const int z = (tile >= T1_TILES);
        if (z) tile -= T1_TILES;
        const float* in  = z ? w2in  : w1in;
        __half*      out = z ? w2out : w1out;
        const int R = z ? IDIM : HDIM;    // rows of input
        const int C = z ? HDIM : IDIM;    // cols of input
        const int tiles_x = C / 32;
        const int c0 = (tile % tiles_x) * 32;
        const int r0 = (tile / tiles_x) * 32;

        const int tx = threadIdx.x & 31;
        const int ty = threadIdx.x >> 5;   // 0..15
        #pragma unroll
        for (int i = ty; i < 32; i += 16)
            shm[i * 33 + tx] = in[(size_t)(r0 + i) * C + c0 + tx];
        __syncthreads();
        #pragma unroll
        for (int i = ty; i < 32; i += 16)
            out[(size_t)(c0 + i) * R + r0 + tx] = __float2half_rn(shm[tx * 33 + i]);
    }
}

// ---------------------------------------------------------------------------
// FP16 GEMM (fp32 accumulate): C[M,N] = A[M,K] @ Bt[N,K]^T
// (+bias, +GELU->half or +fp16 residual->f32)
// CTA tile 128x128x64, 8 warps (4Mx2N), warp tile 32x64, m16n8k16 HMMA.
// 3-stage cp.async pipeline, one __syncthreads per k-iter, 2 CTAs/SM
// (16 warps/SM). Proven best config: 98% of the legacy HMMA.F32 pipe
// rate (0.333 MMA/cyc/SM) — the toolchain's tensor ceiling without
// sm_103a-gated tcgen05.
// ---------------------------------------------------------------------------
#define BM 128
#define BN 128
#define BKH 64                        // halves per K-slab (128 bytes)
#define KSTH 72                       // smem row stride in halves (64 + 8 pad)
#define A_HALVES (BM * KSTH)          // 9216
#define B_HALVES (BN * KSTH)          // 9216
#define STAGE_HALVES (A_HALVES + B_HALVES)   // 18432
#define NSTG 3
#define SMEM_BYTES (NSTG * STAGE_HALVES * 2) // 110592

template <bool GELU>
__global__ void __launch_bounds__(256, 2) gemm_f16(
    const __half* __restrict__ A, const __half* __restrict__ Bt,
    const float* __restrict__ bias, const __half* __restrict__ res,
    void* __restrict__ Cv, int N, int K)
{
    extern __shared__ __half smh[];
    const uint32_t sm0 = (uint32_t)__cvta_generic_to_shared(smh);

    const int tid = threadIdx.x;
    const int warp = tid >> 5, lane = tid & 31;
    const int wm = warp >> 1, wn = warp & 1;     // 4 (M) x 2 (N)
    const int row0 = blockIdx.y * BM;
    const int col0 = blockIdx.x * BN;
    const int g = lane >> 2, tq = lane & 3;

    // ldmatrix per-thread address components (in halves)
    const int a_row = wm * 32 + (lane & 15);
    const int a_k   = (lane >> 4) * 8;
    const int b_row = wn * 64 + ((lane & 7) | ((lane >> 1) & 8));
    const int b_k   = ((lane >> 3) & 1) * 8;

    float acc[2][8][4];
    #pragma unroll
    for (int mi = 0; mi < 2; mi++)
        #pragma unroll
        for (int j = 0; j < 8; j++)
            #pragma unroll
            for (int q = 0; q < 4; q++) acc[mi][j][q] = 0.0f;

    const int nK = K / BKH;

    auto load_stage = [&](int kt, int s) {
        __half* As = smh + s * STAGE_HALVES;
        __half* Bs = As + A_HALVES;
        const __half* Ag = A + (size_t)row0 * K + kt * BKH;
        const __half* Bg = Bt + (size_t)col0 * K + kt * BKH;
        #pragma unroll
        for (int i = 0; i < 4; i++) {          // A: 1024 chunks of 16B (8 halves)
            int c = tid + 256 * i;
            int r = c >> 3, o = (c & 7) * 8;
            cp_async16((uint32_t)__cvta_generic_to_shared(As + r * KSTH + o),
                       Ag + (size_t)r * K + o);
        }
        #pragma unroll
        for (int i = 0; i < 4; i++) {          // B: 1024 chunks of 16B
            int c = tid + 256 * i;
            int r = c >> 3, o = (c & 7) * 8;
            cp_async16((uint32_t)__cvta_generic_to_shared(Bs + r * KSTH + o),
                       Bg + (size_t)r * K + o);
        }
        asm volatile("cp.async.commit_group;\n");
    };

    // prefill 2 stages (tiles 0,1 -> 2 groups)
    load_stage(0, 0);
    load_stage(1, 1);

    for (int kt = 0; kt < nK; kt++) {
        const int s = kt % NSTG;
        // tile kt complete in THIS thread (only tile kt+1's group may pend)
        asm volatile("cp.async.wait_group 1;\n");
        // publish all threads' copies of tile kt; also: everyone is done
        // reading stage (kt-1)%NSTG, which gets overwritten below
        __syncthreads();
        if (kt + 2 < nK) {
            load_stage(kt + 2, (kt + 2) % NSTG);       // commits 1 group
        } else {
            asm volatile("cp.async.commit_group;\n");  // keep group-count invariant
        }

        const uint32_t As_u = sm0 + (s * STAGE_HALVES) * 2;
        const uint32_t Bs_u = As_u + A_HALVES * 2;
        const uint32_t a_addr = As_u + (a_row * KSTH + a_k) * 2;
        const uint32_t b_addr = Bs_u + (b_row * KSTH + b_k) * 2;

        #pragma unroll
        for (int kk = 0; kk < BKH; kk += 16) {
            uint32_t af[2][4], bf[4][4];
            #pragma unroll
            for (int mi = 0; mi < 2; mi++)
                ldsm4(af[mi], a_addr + (mi * 16 * KSTH + kk) * 2);
            #pragma unroll
            for (int p = 0; p < 4; p++)
                ldsm4(bf[p], b_addr + (p * 16 * KSTH + kk) * 2);
            #pragma unroll
            for (int mi = 0; mi < 2; mi++)
                #pragma unroll
                for (int j = 0; j < 8; j++)
                    mma_f16(acc[mi][j], af[mi],
                            bf[j >> 1][(j & 1) * 2], bf[j >> 1][(j & 1) * 2 + 1]);
        }
    }

    // Epilogue: register -> gmem
    #pragma unroll
    for (int mi = 0; mi < 2; mi++) {
        const int r0 = row0 + wm * 32 + mi * 16 + g;
        const int r1 = r0 + 8;
        #pragma unroll
        for (int j = 0; j < 8; j++) {
            const int c = col0 + wn * 64 + j * 8 + tq * 2;
            const float b0 = bias[c], b1 = bias[c + 1];
            float v00 = acc[mi][j][0] + b0;
            float v01 = acc[mi][j][1] + b1;
            float v10 = acc[mi][j][2] + b0;
            float v11 = acc[mi][j][3] + b1;
            if (GELU) {
                __half* Ch = (__half*)Cv;
                v00 = gelu_tanh(v00); v01 = gelu_tanh(v01);
                v10 = gelu_tanh(v10); v11 = gelu_tanh(v11);
                *(__half2*)(Ch + (size_t)r0 * N + c) = __floats2half2_rn(v00, v01);
                *(__half2*)(Ch + (size_t)r1 * N + c) = __floats2half2_rn(v10, v11);
            } else {
                float* Cf = (float*)Cv;
                const float2 ra0 = __half22float2(*(const __half2*)(res + (size_t)r0 * N + c));
                const float2 ra1 = __half22float2(*(const __half2*)(res + (size_t)r1 * N + c));
                v00 += ra0.x; v01 += ra0.y;
                v10 += ra1.x; v11 += ra1.y;
                *(float2*)(Cf + (size_t)r0 * N + c) = make_float2(v00, v01);
                *(float2*)(Cf + (size_t)r1 * N + c) = make_float2(v10, v11);
            }
        }
    }
}

// ---------------------------------------------------------------------------
// Launch
// ---------------------------------------------------------------------------
extern "C" void kernel_launch(void* const* d_in, const int* in_sizes, int n_in,
                              void* d_out, int out_size)
{
    const float* input    = (const float*)d_in[0];
    const float* residual = (const float*)d_in[1];
    const float* bias     = (const float*)d_in[3];
    const float* attn_nw  = (const float*)d_in[4];
    const float* attn_nb  = (const float*)d_in[5];
    const float* inter_w  = (const float*)d_in[6];
    const float* inter_b  = (const float*)d_in[7];
    const float* output_w = (const float*)d_in[8];
    const float* output_b = (const float*)d_in[9];
    float* out = (float*)d_out;

    __half *xn, *ra, *hbuf, *wt1, *wt2;
    cudaGetSymbolAddress((void**)&xn,   g_xnorm);
    cudaGetSymbolAddress((void**)&ra,   g_resadd);
    cudaGetSymbolAddress((void**)&hbuf, g_h);
    cudaGetSymbolAddress((void**)&wt1,  g_wt1);
    cudaGetSymbolAddress((void**)&wt2,  g_wt2);

    cudaFuncSetAttribute(gemm_f16<true>,
                         cudaFuncAttributeMaxDynamicSharedMemorySize, SMEM_BYTES);
    cudaFuncSetAttribute(gemm_f16<false>,
                         cudaFuncAttributeMaxDynamicSharedMemorySize, SMEM_BYTES);

    // 1) ONE prep launch: LN (2 rows/block) + both weight transposes
    prep_kernel<<<PREP_BLOCKS, 512>>>(
        input, residual, bias, attn_nw, attn_nb, xn, ra,
        inter_w, wt1, output_w, wt2);

    // 2) h = gelu(x @ inter_w + inter_b)  [32768,4096] fp16
    gemm_f16<true><<<dim3(IDIM / BN, M_TOK / BM), 256, SMEM_BYTES>>>(
        xn, wt1, inter_b, nullptr, hbuf, IDIM, HDIM);

    // 3) out = h @ output_w + output_b + residual_add  [32768,1024] fp32
    gemm_f16<false><<<dim3(HDIM / BN, M_TOK / BM), 256, SMEM_BYTES>>>(
        hbuf, wt2, output_b, ra, out, HDIM, IDIM);
}